// round 2
// baseline (speedup 1.0000x reference)
#include <cuda_runtime.h>
#include <math_constants.h>

// piecewise_maxpool: conv_output [B=4096, S=256, F=256] f32, e1/e2 [B] i32
// out [B, 3*F]: seg0 = max over s in [0, e1], seg1 = (e1, e2], seg2 = (e2, S)
// Segments guaranteed non-empty by input construction.
//
// Persistent grid-stride version: grid = 148 SMs * 8 CTAs = 1184 (one full
// wave at occupancy 8), eliminating the 3.46-wave quantization tail of the
// grid=4096 launch.

static constexpr int BATCH = 4096;
static constexpr int SEQ   = 256;
static constexpr int FILT  = 256;   // 64 float4 per position
static constexpr int GRID  = 148 * 8;

__device__ __forceinline__ float4 fmax4(float4 a, float4 b) {
    return make_float4(fmaxf(a.x, b.x), fmaxf(a.y, b.y),
                       fmaxf(a.z, b.z), fmaxf(a.w, b.w));
}

__global__ __launch_bounds__(256, 8)
void piecewise_maxpool_kernel(const float* __restrict__ x,
                              const int*   __restrict__ e1,
                              const int*   __restrict__ e2,
                              float*       __restrict__ out)
{
    const int t = threadIdx.x;
    const int g = t & 63;    // float4 group within filter dim (filters 4g..4g+3)
    const int p = t >> 6;    // position sub-offset 0..3

    __shared__ float4 red[3][256];   // 12 KB

    const float4 ninf = make_float4(-CUDART_INF_F, -CUDART_INF_F,
                                    -CUDART_INF_F, -CUDART_INF_F);

    for (int b = blockIdx.x; b < BATCH; b += GRID) {
        const int c1 = __ldg(&e1[b]);
        const int c2 = __ldg(&e2[b]);

        const float4* __restrict__ row =
            reinterpret_cast<const float4*>(x + (size_t)b * SEQ * FILT);

        float4 m0 = ninf, m1 = ninf, m2 = ninf;

        // positions s = 4*i + p: warp-uniform s, 512B contiguous per warp
        // per load, 4KB per CTA per iteration.
        #pragma unroll 4
        for (int i = 0; i < SEQ / 4; ++i) {
            const int s = i * 4 + p;
            const float4 v = __ldcs(&row[s * (FILT / 4) + g]);  // stream, no reuse
            const int seg = (s > c1) + (s > c2);                // warp-uniform
            if (seg == 0)      m0 = fmax4(m0, v);
            else if (seg == 1) m1 = fmax4(m1, v);
            else               m2 = fmax4(m2, v);
        }

        red[0][t] = m0;
        red[1][t] = m1;
        red[2][t] = m2;
        __syncthreads();

        if (t < 192) {
            const int seg = t >> 6;
            const int gg  = t & 63;
            float4 r = fmax4(fmax4(red[seg][gg],       red[seg][64 + gg]),
                             fmax4(red[seg][128 + gg], red[seg][192 + gg]));
            float4* __restrict__ o =
                reinterpret_cast<float4*>(out + (size_t)b * 3 * FILT + seg * FILT);
            o[gg] = r;
        }
        __syncthreads();   // protect red[] before next row overwrites it
    }
}

extern "C" void kernel_launch(void* const* d_in, const int* in_sizes, int n_in,
                              void* d_out, int out_size)
{
    const float* x  = (const float*)d_in[0];
    const int*   e1 = (const int*)d_in[1];
    const int*   e2 = (const int*)d_in[2];
    float*       o  = (float*)d_out;

    piecewise_maxpool_kernel<<<GRID, 256>>>(x, e1, e2, o);
}

// round 3
// speedup vs baseline: 1.0246x; 1.0246x over previous
#include <cuda_runtime.h>
#include <math_constants.h>

// piecewise_maxpool: conv_output [B=4096, S=256, F=256] f32, e1/e2 [B] i32
// out [B, 3*F]: seg0 = max over s in [0, e1], seg1 = (e1, e2], seg2 = (e2, S)
// Segments guaranteed non-empty by input construction.
//
// R3: back to one-row-per-CTA (grid=4096, scheduler backfills fine per R2),
// unroll 8 with relaxed reg budget (occ 6) to deepen the per-thread LDG batch
// and close DRAM issue bubbles.

static constexpr int BATCH = 4096;
static constexpr int SEQ   = 256;
static constexpr int FILT  = 256;   // 64 float4 per position

__device__ __forceinline__ float4 fmax4(float4 a, float4 b) {
    return make_float4(fmaxf(a.x, b.x), fmaxf(a.y, b.y),
                       fmaxf(a.z, b.z), fmaxf(a.w, b.w));
}

__global__ __launch_bounds__(256, 6)
void piecewise_maxpool_kernel(const float* __restrict__ x,
                              const int*   __restrict__ e1,
                              const int*   __restrict__ e2,
                              float*       __restrict__ out)
{
    const int b = blockIdx.x;
    const int t = threadIdx.x;
    const int g = t & 63;    // float4 group within filter dim (filters 4g..4g+3)
    const int p = t >> 6;    // position sub-offset 0..3

    const int c1 = __ldg(&e1[b]);
    const int c2 = __ldg(&e2[b]);

    const float4* __restrict__ row =
        reinterpret_cast<const float4*>(x + (size_t)b * SEQ * FILT);

    const float4 ninf = make_float4(-CUDART_INF_F, -CUDART_INF_F,
                                    -CUDART_INF_F, -CUDART_INF_F);
    float4 m0 = ninf, m1 = ninf, m2 = ninf;

    // positions s = 4*i + p: warp-uniform s, 512B contiguous per warp per
    // load. Unroll 8 -> 8 independent LDG.E.128 front-batched per thread.
    #pragma unroll 8
    for (int i = 0; i < SEQ / 4; ++i) {
        const int s = i * 4 + p;
        const float4 v = __ldg(&row[s * (FILT / 4) + g]);
        const int seg = (s > c1) + (s > c2);   // warp-uniform
        if (seg == 0)      m0 = fmax4(m0, v);
        else if (seg == 1) m1 = fmax4(m1, v);
        else               m2 = fmax4(m2, v);
    }

    // Reduce the 4 position-partials (threads p=0..3) per filter group.
    __shared__ float4 red[3][256];   // 12 KB
    red[0][t] = m0;
    red[1][t] = m1;
    red[2][t] = m2;
    __syncthreads();

    if (t < 192) {
        const int seg = t >> 6;
        const int gg  = t & 63;
        float4 r = fmax4(fmax4(red[seg][gg],       red[seg][64 + gg]),
                         fmax4(red[seg][128 + gg], red[seg][192 + gg]));
        float4* __restrict__ o =
            reinterpret_cast<float4*>(out + (size_t)b * 3 * FILT + seg * FILT);
        o[gg] = r;
    }
}

extern "C" void kernel_launch(void* const* d_in, const int* in_sizes, int n_in,
                              void* d_out, int out_size)
{
    const float* x  = (const float*)d_in[0];
    const int*   e1 = (const int*)d_in[1];
    const int*   e2 = (const int*)d_in[2];
    float*       o  = (float*)d_out;

    piecewise_maxpool_kernel<<<BATCH, 256>>>(x, e1, e2, o);
}

// round 4
// speedup vs baseline: 1.1706x; 1.1425x over previous
#include <cuda_runtime.h>
#include <cstdint>
#include <math_constants.h>

// piecewise_maxpool: conv_output [B=4096, S=256, F=256] f32, e1/e2 [B] i32
// out [B, 3*F]: seg0 = [0, e1], seg1 = (e1, e2], seg2 = (e2, S). Non-empty.
//
// R4: TMA bulk-copy (cp.async.bulk, UBLKCP) global->smem pipeline to bypass
// the L1tex/MSHR path that appears to cap the LDG version at ~6.05 TB/s.

static constexpr int BATCH = 4096;
static constexpr int SEQ   = 256;
static constexpr int FILT  = 256;
static constexpr int CHUNK_POS   = 8;                          // positions per chunk
static constexpr int CHUNK_BYTES = CHUNK_POS * FILT * 4;       // 8192
static constexpr int CHUNK_F4    = CHUNK_BYTES / 16;           // 512 float4
static constexpr int NCHUNK      = SEQ / CHUNK_POS;            // 32
static constexpr int STAGES      = 4;

__device__ __forceinline__ uint32_t smem_u32(const void* p) {
    return (uint32_t)__cvta_generic_to_shared(p);
}
__device__ __forceinline__ void mbar_init(uint32_t a, uint32_t n) {
    asm volatile("mbarrier.init.shared.b64 [%0], %1;" :: "r"(a), "r"(n) : "memory");
}
__device__ __forceinline__ void mbar_expect_tx(uint32_t a, uint32_t bytes) {
    asm volatile("mbarrier.arrive.expect_tx.shared.b64 _, [%0], %1;"
                 :: "r"(a), "r"(bytes) : "memory");
}
__device__ __forceinline__ void mbar_wait(uint32_t a, uint32_t parity) {
    uint32_t done;
    asm volatile(
        "{\n\t.reg .pred p;\n\t"
        "mbarrier.try_wait.parity.acquire.cta.shared::cta.b64 p, [%1], %2;\n\t"
        "selp.b32 %0, 1, 0, p;\n\t}"
        : "=r"(done) : "r"(a), "r"(parity) : "memory");
    if (!done) {
        asm volatile(
            "{\n\t.reg .pred P1;\n\t"
            "WL_%=:\n\t"
            "mbarrier.try_wait.parity.acquire.cta.shared::cta.b64 P1, [%0], %1, 0x989680;\n\t"
            "@P1 bra.uni WD_%=;\n\t"
            "bra.uni WL_%=;\n\t"
            "WD_%=:\n\t}"
            :: "r"(a), "r"(parity) : "memory");
    }
}
__device__ __forceinline__ void bulk_ld(uint32_t dst, const void* src,
                                        uint32_t bytes, uint32_t mbar) {
    asm volatile(
        "cp.async.bulk.shared::cta.global.mbarrier::complete_tx::bytes "
        "[%0], [%1], %2, [%3];"
        :: "r"(dst), "l"(src), "r"(bytes), "r"(mbar) : "memory");
}

__device__ __forceinline__ float4 fmax4(float4 a, float4 b) {
    return make_float4(fmaxf(a.x, b.x), fmaxf(a.y, b.y),
                       fmaxf(a.z, b.z), fmaxf(a.w, b.w));
}

__global__ __launch_bounds__(256, 6)
void piecewise_maxpool_tma_kernel(const float* __restrict__ x,
                                  const int*   __restrict__ e1,
                                  const int*   __restrict__ e2,
                                  float*       __restrict__ out)
{
    __shared__ __align__(1024) float4 buf[STAGES][CHUNK_F4];   // 32 KB ring
    __shared__ uint64_t mbar[STAGES];

    const int b = blockIdx.x;
    const int t = threadIdx.x;
    const int g = t & 63;    // float4 column (filters 4g..4g+3)
    const int p = t >> 6;    // position sub-offset 0..3

    const int c1 = __ldg(&e1[b]);
    const int c2 = __ldg(&e2[b]);
    const char* __restrict__ src =
        reinterpret_cast<const char*>(x + (size_t)b * SEQ * FILT);

    if (t == 0) {
        #pragma unroll
        for (int s = 0; s < STAGES; ++s) mbar_init(smem_u32(&mbar[s]), 1);
        // make inits visible to the async proxy before first TMA completes
        asm volatile("fence.proxy.async.shared::cta;" ::: "memory");
        #pragma unroll
        for (int s = 0; s < STAGES; ++s) {
            mbar_expect_tx(smem_u32(&mbar[s]), CHUNK_BYTES);
            bulk_ld(smem_u32(&buf[s][0]), src + (size_t)s * CHUNK_BYTES,
                    CHUNK_BYTES, smem_u32(&mbar[s]));
        }
    }
    __syncthreads();   // mbar init visible to all waiters

    const float4 ninf = make_float4(-CUDART_INF_F, -CUDART_INF_F,
                                    -CUDART_INF_F, -CUDART_INF_F);
    float4 m0 = ninf, m1 = ninf, m2 = ninf;

    for (int c = 0; c < NCHUNK; ++c) {
        const int s = c & (STAGES - 1);
        mbar_wait(smem_u32(&mbar[s]), (c >> 2) & 1);

        // consume: thread covers local positions p and p+4 of this 8-pos chunk
        #pragma unroll
        for (int j = 0; j < 2; ++j) {
            const int lp = p + 4 * j;
            const int gs = c * CHUNK_POS + lp;
            const float4 v = buf[s][lp * 64 + g];
            const int seg = (gs > c1) + (gs > c2);   // warp-uniform
            if (seg == 0)      m0 = fmax4(m0, v);
            else if (seg == 1) m1 = fmax4(m1, v);
            else               m2 = fmax4(m2, v);
        }
        __syncthreads();   // stage s fully consumed by all threads

        const int nc = c + STAGES;
        if (t == 0 && nc < NCHUNK) {
            asm volatile("fence.proxy.async.shared::cta;" ::: "memory");
            mbar_expect_tx(smem_u32(&mbar[s]), CHUNK_BYTES);
            bulk_ld(smem_u32(&buf[s][0]), src + (size_t)nc * CHUNK_BYTES,
                    CHUNK_BYTES, smem_u32(&mbar[s]));
        }
    }

    // Final reduction: reuse the ring buffer as scratch (3*256 float4 = 12 KB).
    float4* red = &buf[0][0];
    red[t]       = m0;
    red[256 + t] = m1;
    red[512 + t] = m2;
    __syncthreads();

    if (t < 192) {
        const int seg = t >> 6;
        const int gg  = t & 63;
        const float4* rs = red + seg * 256;
        float4 r = fmax4(fmax4(rs[gg],       rs[64 + gg]),
                         fmax4(rs[128 + gg], rs[192 + gg]));
        float4* __restrict__ o =
            reinterpret_cast<float4*>(out + (size_t)b * 3 * FILT + seg * FILT);
        o[gg] = r;
    }
}

extern "C" void kernel_launch(void* const* d_in, const int* in_sizes, int n_in,
                              void* d_out, int out_size)
{
    const float* x  = (const float*)d_in[0];
    const int*   e1 = (const int*)d_in[1];
    const int*   e2 = (const int*)d_in[2];
    float*       o  = (float*)d_out;

    piecewise_maxpool_tma_kernel<<<BATCH, 256>>>(x, e1, e2, o);
}

// round 5
// speedup vs baseline: 1.1715x; 1.0008x over previous
#include <cuda_runtime.h>
#include <cstdint>
#include <math_constants.h>

// piecewise_maxpool: conv_output [B=4096, S=256, F=256] f32, e1/e2 [B] i32
// out [B, 3*F]: seg0 = [0, e1], seg1 = (e1, e2], seg2 = (e2, S). Non-empty.
//
// R5: TMA bulk-copy pipeline, 16KB chunks x 2 stages (was 8KB x 4) to halve
// the per-chunk mbarrier-wait + BAR.SYNC overhead that accounted for the
// ~10% gap below DRAM peak.

static constexpr int BATCH = 4096;
static constexpr int SEQ   = 256;
static constexpr int FILT  = 256;
static constexpr int CHUNK_POS   = 16;                         // positions per chunk
static constexpr int CHUNK_BYTES = CHUNK_POS * FILT * 4;       // 16384
static constexpr int CHUNK_F4    = CHUNK_BYTES / 16;           // 1024 float4
static constexpr int NCHUNK      = SEQ / CHUNK_POS;            // 16
static constexpr int STAGES      = 2;

__device__ __forceinline__ uint32_t smem_u32(const void* p) {
    return (uint32_t)__cvta_generic_to_shared(p);
}
__device__ __forceinline__ void mbar_init(uint32_t a, uint32_t n) {
    asm volatile("mbarrier.init.shared.b64 [%0], %1;" :: "r"(a), "r"(n) : "memory");
}
__device__ __forceinline__ void mbar_expect_tx(uint32_t a, uint32_t bytes) {
    asm volatile("mbarrier.arrive.expect_tx.shared.b64 _, [%0], %1;"
                 :: "r"(a), "r"(bytes) : "memory");
}
__device__ __forceinline__ void mbar_wait(uint32_t a, uint32_t parity) {
    uint32_t done;
    asm volatile(
        "{\n\t.reg .pred p;\n\t"
        "mbarrier.try_wait.parity.acquire.cta.shared::cta.b64 p, [%1], %2;\n\t"
        "selp.b32 %0, 1, 0, p;\n\t}"
        : "=r"(done) : "r"(a), "r"(parity) : "memory");
    if (!done) {
        asm volatile(
            "{\n\t.reg .pred P1;\n\t"
            "WL_%=:\n\t"
            "mbarrier.try_wait.parity.acquire.cta.shared::cta.b64 P1, [%0], %1, 0x989680;\n\t"
            "@P1 bra.uni WD_%=;\n\t"
            "bra.uni WL_%=;\n\t"
            "WD_%=:\n\t}"
            :: "r"(a), "r"(parity) : "memory");
    }
}
__device__ __forceinline__ void bulk_ld(uint32_t dst, const void* src,
                                        uint32_t bytes, uint32_t mbar) {
    asm volatile(
        "cp.async.bulk.shared::cta.global.mbarrier::complete_tx::bytes "
        "[%0], [%1], %2, [%3];"
        :: "r"(dst), "l"(src), "r"(bytes), "r"(mbar) : "memory");
}

__device__ __forceinline__ float4 fmax4(float4 a, float4 b) {
    return make_float4(fmaxf(a.x, b.x), fmaxf(a.y, b.y),
                       fmaxf(a.z, b.z), fmaxf(a.w, b.w));
}

__global__ __launch_bounds__(256, 6)
void piecewise_maxpool_tma_kernel(const float* __restrict__ x,
                                  const int*   __restrict__ e1,
                                  const int*   __restrict__ e2,
                                  float*       __restrict__ out)
{
    __shared__ __align__(1024) float4 buf[STAGES][CHUNK_F4];   // 32 KB ring
    __shared__ uint64_t mbar[STAGES];

    const int b = blockIdx.x;
    const int t = threadIdx.x;
    const int g = t & 63;    // float4 column (filters 4g..4g+3)
    const int p = t >> 6;    // position sub-offset 0..3

    const int c1 = __ldg(&e1[b]);
    const int c2 = __ldg(&e2[b]);
    const char* __restrict__ src =
        reinterpret_cast<const char*>(x + (size_t)b * SEQ * FILT);

    if (t == 0) {
        #pragma unroll
        for (int s = 0; s < STAGES; ++s) mbar_init(smem_u32(&mbar[s]), 1);
        asm volatile("fence.proxy.async.shared::cta;" ::: "memory");
        #pragma unroll
        for (int s = 0; s < STAGES; ++s) {
            mbar_expect_tx(smem_u32(&mbar[s]), CHUNK_BYTES);
            bulk_ld(smem_u32(&buf[s][0]), src + (size_t)s * CHUNK_BYTES,
                    CHUNK_BYTES, smem_u32(&mbar[s]));
        }
    }
    __syncthreads();   // mbar init visible to all waiters

    const float4 ninf = make_float4(-CUDART_INF_F, -CUDART_INF_F,
                                    -CUDART_INF_F, -CUDART_INF_F);
    float4 m0 = ninf, m1 = ninf, m2 = ninf;

    for (int c = 0; c < NCHUNK; ++c) {
        const int s = c & (STAGES - 1);
        mbar_wait(smem_u32(&mbar[s]), (c >> 1) & 1);

        // consume: thread covers local positions p, p+4, p+8, p+12
        #pragma unroll
        for (int j = 0; j < CHUNK_POS / 4; ++j) {
            const int lp = p + 4 * j;
            const int gs = c * CHUNK_POS + lp;
            const float4 v = buf[s][lp * 64 + g];
            const int seg = (gs > c1) + (gs > c2);   // warp-uniform
            if (seg == 0)      m0 = fmax4(m0, v);
            else if (seg == 1) m1 = fmax4(m1, v);
            else               m2 = fmax4(m2, v);
        }
        __syncthreads();   // stage s fully consumed by all threads

        const int nc = c + STAGES;
        if (t == 0 && nc < NCHUNK) {
            asm volatile("fence.proxy.async.shared::cta;" ::: "memory");
            mbar_expect_tx(smem_u32(&mbar[s]), CHUNK_BYTES);
            bulk_ld(smem_u32(&buf[s][0]), src + (size_t)nc * CHUNK_BYTES,
                    CHUNK_BYTES, smem_u32(&mbar[s]));
        }
    }

    // Final reduction: reuse the ring buffer as scratch (3*256 float4 = 12 KB).
    float4* red = &buf[0][0];
    red[t]       = m0;
    red[256 + t] = m1;
    red[512 + t] = m2;
    __syncthreads();

    if (t < 192) {
        const int seg = t >> 6;
        const int gg  = t & 63;
        const float4* rs = red + seg * 256;
        float4 r = fmax4(fmax4(rs[gg],       rs[64 + gg]),
                         fmax4(rs[128 + gg], rs[192 + gg]));
        float4* __restrict__ o =
            reinterpret_cast<float4*>(out + (size_t)b * 3 * FILT + seg * FILT);
        o[gg] = r;
    }
}

extern "C" void kernel_launch(void* const* d_in, const int* in_sizes, int n_in,
                              void* d_out, int out_size)
{
    const float* x  = (const float*)d_in[0];
    const int*   e1 = (const int*)d_in[1];
    const int*   e2 = (const int*)d_in[2];
    float*       o  = (float*)d_out;

    piecewise_maxpool_tma_kernel<<<BATCH, 256>>>(x, e1, e2, o);
}